// round 1
// baseline (speedup 1.0000x reference)
#include <cuda_runtime.h>
#include <math.h>

#define NN 100000
#define NE 3200000

// ---------------- device scratch (no runtime allocation allowed) ----------------
__device__ int   g_flag64;
__device__ int   g_deg[NN];
__device__ int   g_rowptr[NN + 1];
__device__ int   g_cursor[NN];
__device__ int   g_srcA[NE];
__device__ int   g_dstA[NE];
__device__ int   g_bsum[128];
__device__ int   g_boff[128];
__device__ int2  g_csr[NE];            // {src, weight-as-bits}, bucketed by dst
__device__ float g_t0[NN * 8];         // x@W1
__device__ float g_t1[NN * 16];        // relu(agg1+b1)@W2
__device__ float g_t2[NN * 8];         // relu(agg2+b2)@W3
__device__ float g_t3[NN * 16];        // relu(agg3+b3)@W4 (padded to 16, cols 10..15 = 0)

// ---------------- dtype detection: int64 vs int32 edge_index ----------------
__global__ void k_detect(const int* __restrict__ ei) {
    int v = 0;
    for (int i = threadIdx.x; i < 512; i += 32) v |= ei[2 * i + 1];
    for (int o = 16; o; o >>= 1) v |= __shfl_xor_sync(0xffffffffu, v, o);
    if (threadIdx.x == 0) g_flag64 = (v == 0) ? 1 : 0;  // all-high-words-zero => int64
}

__global__ void k_zero() {
    int i = blockIdx.x * blockDim.x + threadIdx.x;
    if (i < NN) g_deg[i] = 0;
}

__global__ void k_convert(const int* __restrict__ ei) {
    int e = blockIdx.x * blockDim.x + threadIdx.x;
    if (e >= NE) return;
    int src, dst;
    if (g_flag64) { src = ei[2 * e]; dst = ei[2 * (NE + e)]; }
    else          { src = ei[e];     dst = ei[NE + e]; }
    g_srcA[e] = src;
    g_dstA[e] = dst;
    atomicAdd(&g_deg[dst], 1);
}

// ---------------- exclusive scan of degrees -> rowptr (3 kernels) ----------------
__global__ void k_scanA() {
    __shared__ int wsum[32];
    int i = blockIdx.x * 1024 + threadIdx.x;
    int lane = threadIdx.x & 31, wid = threadIdx.x >> 5;
    int val = (i < NN) ? g_deg[i] : 0;
    int v = val;
    #pragma unroll
    for (int o = 1; o < 32; o <<= 1) {
        int u = __shfl_up_sync(0xffffffffu, v, o);
        if (lane >= o) v += u;
    }
    if (lane == 31) wsum[wid] = v;
    __syncthreads();
    if (wid == 0) {
        int w = wsum[lane];
        #pragma unroll
        for (int o = 1; o < 32; o <<= 1) {
            int u = __shfl_up_sync(0xffffffffu, w, o);
            if (lane >= o) w += u;
        }
        wsum[lane] = w;
    }
    __syncthreads();
    int incl = v + (wid ? wsum[wid - 1] : 0);
    if (i < NN) g_rowptr[i] = incl - val;          // block-local exclusive
    if (threadIdx.x == 1023) g_bsum[blockIdx.x] = incl;
}

__global__ void k_scanB() {
    __shared__ int s[128];
    int t = threadIdx.x;
    s[t] = (t < 98) ? g_bsum[t] : 0;
    __syncthreads();
    if (t == 0) {
        int r = 0;
        for (int i = 0; i < 98; i++) { int x = s[i]; s[i] = r; r += x; }
    }
    __syncthreads();
    if (t < 98) g_boff[t] = s[t];
}

__global__ void k_scanC() {
    int i = blockIdx.x * blockDim.x + threadIdx.x;
    if (i < NN) {
        int rp = g_rowptr[i] + g_boff[i >> 10];
        g_rowptr[i] = rp;
        g_cursor[i] = rp;
    }
    if (i == 0) g_rowptr[NN] = NE;
}

__global__ void k_scatter(const float* __restrict__ ew) {
    int e = blockIdx.x * blockDim.x + threadIdx.x;
    if (e >= NE) return;
    int dst = g_dstA[e];
    int pos = atomicAdd(&g_cursor[dst], 1);
    g_csr[pos] = make_int2(g_srcA[e], __float_as_int(ew[e]));
}

// ---------------- GEMM: t0 = x @ W1  (N x 512 @ 512 x 8), warp per 4 nodes ----------------
__global__ void k_gemm1(const float* __restrict__ x, const float* __restrict__ W1) {
    __shared__ float Wt[8 * 512];  // Wt[o*512 + k] = W1[k*8 + o]
    for (int idx = threadIdx.x; idx < 4096; idx += 256) {
        int o = idx >> 9, k = idx & 511;
        Wt[idx] = W1[k * 8 + o];
    }
    __syncthreads();
    int warp = (blockIdx.x * 256 + threadIdx.x) >> 5;
    int lane = threadIdx.x & 31;
    int nb = warp * 4;  // 25000 warps exactly cover 100000 nodes

    float acc[4][8];
    #pragma unroll
    for (int i = 0; i < 4; i++)
        #pragma unroll
        for (int o = 0; o < 8; o++) acc[i][o] = 0.f;

    #pragma unroll
    for (int j = 0; j < 4; j++) {
        int c = 4 * lane + 128 * j;
        float4 xv[4];
        #pragma unroll
        for (int i = 0; i < 4; i++)
            xv[i] = *(const float4*)(x + (size_t)(nb + i) * 512 + c);
        #pragma unroll
        for (int o = 0; o < 8; o++) {
            float4 wv = *(const float4*)(Wt + o * 512 + c);
            #pragma unroll
            for (int i = 0; i < 4; i++)
                acc[i][o] += xv[i].x * wv.x + xv[i].y * wv.y + xv[i].z * wv.z + xv[i].w * wv.w;
        }
    }

    float myval = 0.f;
    #pragma unroll
    for (int i = 0; i < 4; i++)
        #pragma unroll
        for (int o = 0; o < 8; o++) {
            float r = acc[i][o];
            #pragma unroll
            for (int off = 16; off; off >>= 1) r += __shfl_xor_sync(0xffffffffu, r, off);
            if (lane == i * 8 + o) myval = r;
        }
    g_t0[(size_t)nb * 8 + lane] = myval;  // fully coalesced 128B store
}

// ---------------- fused aggregation + bias + relu + next tiny GEMM ----------------
// GROUP lanes per node, lane f accumulates feature f. Epilogue: h = relu(acc+b),
// then out[o] = sum_f h[f]*W[f][o] via intra-group shfl, written to tout.
template <int GROUP, int OUTC, int OPL>
__global__ void k_agg(const float* __restrict__ tin,
                      const float* __restrict__ Wn, int wcols,
                      const float* __restrict__ bias, int blen,
                      float* __restrict__ tout) {
    __shared__ float Ws[16 * 16];   // padded [GROUP][16]
    __shared__ float bs[16];
    for (int idx = threadIdx.x; idx < GROUP * 16; idx += blockDim.x) {
        int k = idx >> 4, o = idx & 15;
        Ws[idx] = (o < wcols) ? Wn[k * wcols + o] : 0.f;
    }
    if (threadIdx.x < 16) bs[threadIdx.x] = (threadIdx.x < blen) ? bias[threadIdx.x] : 0.f;
    __syncthreads();

    int t = blockIdx.x * blockDim.x + threadIdx.x;
    int gid = t / GROUP, f = t % GROUP;   // grid sized exactly: gid < NN always

    int s = g_rowptr[gid], e = g_rowptr[gid + 1];
    float acc = 0.f;
    int i = s;
    for (; i + 3 < e; i += 4) {
        int2 a = g_csr[i], b = g_csr[i + 1], c = g_csr[i + 2], d = g_csr[i + 3];
        float p0 = tin[(size_t)a.x * GROUP + f] * __int_as_float(a.y);
        float p1 = tin[(size_t)b.x * GROUP + f] * __int_as_float(b.y);
        float p2 = tin[(size_t)c.x * GROUP + f] * __int_as_float(c.y);
        float p3 = tin[(size_t)d.x * GROUP + f] * __int_as_float(d.y);
        acc += (p0 + p1) + (p2 + p3);
    }
    for (; i < e; i++) {
        int2 a = g_csr[i];
        acc += tin[(size_t)a.x * GROUP + f] * __int_as_float(a.y);
    }

    float h = fmaxf(acc + bs[f], 0.f);
    float out[OPL];
    #pragma unroll
    for (int j = 0; j < OPL; j++) out[j] = 0.f;
    #pragma unroll
    for (int k = 0; k < GROUP; k++) {
        float hk = __shfl_sync(0xffffffffu, h, k, GROUP);
        #pragma unroll
        for (int j = 0; j < OPL; j++) out[j] += hk * Ws[k * 16 + f + j * GROUP];
    }
    #pragma unroll
    for (int j = 0; j < OPL; j++) {
        int o = f + j * GROUP;
        if (o < OUTC) tout[(size_t)gid * OUTC + o] = out[j];
    }
}

// last layer: aggregate t3 (16-wide, cols 10..15 zero), +b4, log_softmax over 10 classes
__global__ void k_agg_last(const float* __restrict__ tin,
                           const float* __restrict__ bias,
                           float* __restrict__ out) {
    __shared__ float bs[16];
    if (threadIdx.x < 16) bs[threadIdx.x] = (threadIdx.x < 10) ? bias[threadIdx.x] : 0.f;
    __syncthreads();

    int t = blockIdx.x * blockDim.x + threadIdx.x;
    int gid = t >> 4, f = t & 15;

    int s = g_rowptr[gid], e = g_rowptr[gid + 1];
    float acc = 0.f;
    int i = s;
    for (; i + 3 < e; i += 4) {
        int2 a = g_csr[i], b = g_csr[i + 1], c = g_csr[i + 2], d = g_csr[i + 3];
        float p0 = tin[(size_t)a.x * 16 + f] * __int_as_float(a.y);
        float p1 = tin[(size_t)b.x * 16 + f] * __int_as_float(b.y);
        float p2 = tin[(size_t)c.x * 16 + f] * __int_as_float(c.y);
        float p3 = tin[(size_t)d.x * 16 + f] * __int_as_float(d.y);
        acc += (p0 + p1) + (p2 + p3);
    }
    for (; i < e; i++) {
        int2 a = g_csr[i];
        acc += tin[(size_t)a.x * 16 + f] * __int_as_float(a.y);
    }

    float v = acc + bs[f];
    float vm = (f < 10) ? v : -INFINITY;
    #pragma unroll
    for (int off = 8; off; off >>= 1) vm = fmaxf(vm, __shfl_xor_sync(0xffffffffu, vm, off, 16));
    float ex = (f < 10) ? expf(v - vm) : 0.f;
    float se = ex;
    #pragma unroll
    for (int off = 8; off; off >>= 1) se += __shfl_xor_sync(0xffffffffu, se, off, 16);
    if (f < 10) out[(size_t)gid * 10 + f] = v - vm - logf(se);
}

// ---------------- launch ----------------
extern "C" void kernel_launch(void* const* d_in, const int* in_sizes, int n_in,
                              void* d_out, int out_size) {
    const float* x  = (const float*)d_in[0];
    const int*   ei = (const int*)d_in[1];
    const float* ew = (const float*)d_in[2];
    const float* W1 = (const float*)d_in[3];
    const float* b1 = (const float*)d_in[4];
    const float* W2 = (const float*)d_in[5];
    const float* b2 = (const float*)d_in[6];
    const float* W3 = (const float*)d_in[7];
    const float* b3 = (const float*)d_in[8];
    const float* W4 = (const float*)d_in[9];
    const float* b4 = (const float*)d_in[10];
    float* out = (float*)d_out;

    void *t0p, *t1p, *t2p, *t3p;
    cudaGetSymbolAddress(&t0p, g_t0);
    cudaGetSymbolAddress(&t1p, g_t1);
    cudaGetSymbolAddress(&t2p, g_t2);
    cudaGetSymbolAddress(&t3p, g_t3);

    k_detect<<<1, 32>>>(ei);
    k_zero<<<(NN + 255) / 256, 256>>>();
    k_convert<<<NE / 256, 256>>>(ei);
    k_scanA<<<98, 1024>>>();
    k_scanB<<<1, 128>>>();
    k_scanC<<<(NN + 255) / 256, 256>>>();
    k_scatter<<<NE / 256, 256>>>(ew);

    k_gemm1<<<3125, 256>>>(x, W1);                                   // t0 = x@W1 (N x 8)

    k_agg<8, 16, 2><<<NN * 8 / 256, 256>>>((const float*)t0p, W2, 16, b1, 8,  (float*)t1p);
    k_agg<16, 8, 1><<<NN * 16 / 256, 256>>>((const float*)t1p, W3, 8,  b2, 16, (float*)t2p);
    k_agg<8, 16, 2><<<NN * 8 / 256, 256>>>((const float*)t2p, W4, 10, b3, 8,  (float*)t3p);
    k_agg_last<<<NN * 16 / 256, 256>>>((const float*)t3p, b4, out);
}

// round 5
// speedup vs baseline: 1.0556x; 1.0556x over previous
#include <cuda_runtime.h>
#include <cuda_fp16.h>
#include <math.h>

#define NN 100000
#define NE 3200000

// ---------------- device scratch ----------------
__device__ int    g_flag64;
__device__ int    g_deg[NN];
__device__ int    g_rowptr[NN + 1];
__device__ int    g_cursor[NN];
__device__ int    g_bsum[128];
__device__ int2   g_csr[NE];           // {src, weight-bits}, bucketed by dst
__device__ float  g_t0[NN * 8];        // x@W1                     (fp32, 8-wide)
__device__ __half g_h1[NN * 16];       // relu(agg1+b1)@W2         (fp16, 16-wide)
__device__ float  g_t2[NN * 8];        // relu(agg2+b2)@W3         (fp32, 8-wide)
__device__ __half g_h3[NN * 16];       // relu(agg3+b3)@W4 pad16   (fp16, 16-wide)

// ---------------- dtype detection: int64 vs int32 edge_index ----------------
__global__ void k_detect(const int* __restrict__ ei) {
    int v = 0;
    for (int i = threadIdx.x; i < 512; i += 32) v |= ei[2 * i + 1];
    for (int o = 16; o; o >>= 1) v |= __shfl_xor_sync(0xffffffffu, v, o);
    if (threadIdx.x == 0) g_flag64 = (v == 0) ? 1 : 0;
}

// ---------------- degree count (reads only dst half of edge_index) ----------------
__global__ void k_count(const int* __restrict__ ei) {
    int e = blockIdx.x * blockDim.x + threadIdx.x;  // NE divisible by 256
    int dst = g_flag64 ? ei[2 * (NE + e)] : ei[NE + e];
    atomicAdd(&g_deg[dst], 1);
}

// ---------------- scan A: block-local exclusive scan + block sums ----------------
__global__ void k_scanA() {
    __shared__ int wsum[32];
    int i = blockIdx.x * 1024 + threadIdx.x;
    int lane = threadIdx.x & 31, wid = threadIdx.x >> 5;
    int val = (i < NN) ? g_deg[i] : 0;
    int v = val;
    #pragma unroll
    for (int o = 1; o < 32; o <<= 1) {
        int u = __shfl_up_sync(0xffffffffu, v, o);
        if (lane >= o) v += u;
    }
    if (lane == 31) wsum[wid] = v;
    __syncthreads();
    if (wid == 0) {
        int w = wsum[lane];
        #pragma unroll
        for (int o = 1; o < 32; o <<= 1) {
            int u = __shfl_up_sync(0xffffffffu, w, o);
            if (lane >= o) w += u;
        }
        wsum[lane] = w;
    }
    __syncthreads();
    int incl = v + (wid ? wsum[wid - 1] : 0);
    if (i < NN) g_rowptr[i] = incl - val;
    if (threadIdx.x == 1023) g_bsum[blockIdx.x] = incl;
}

// ---------------- scan C (scanB folded in: every block scans the 98 block sums) ----
__global__ void k_scanCB() {
    __shared__ int s[128];
    int t = threadIdx.x;
    if (t < 128) s[t] = (t < 98) ? g_bsum[t] : 0;
    __syncthreads();
    if (t == 0) {
        int r = 0;
        for (int i = 0; i < 98; i++) { int x = s[i]; s[i] = r; r += x; }
    }
    __syncthreads();
    int i = blockIdx.x * 256 + t;
    if (i < NN) {
        int rp = g_rowptr[i] + s[i >> 10];
        g_rowptr[i] = rp;
        g_cursor[i] = rp;
    }
    if (i == 0) g_rowptr[NN] = NE;
}

// ---------------- fused: gemm1 (blocks 0..3124) || scatter (blocks 3125..15624) ----
// gemm1: t0 = x @ W1  (100000x512 @ 512x8), warp per 4 nodes.
// scatter: place {src, w} into g_csr at cursor positions.
__global__ void k_fused(const float* __restrict__ x, const float* __restrict__ W1,
                        const int* __restrict__ ei, const float* __restrict__ ew) {
    __shared__ float Wt[8 * 512];
    if (blockIdx.x < 3125) {
        for (int idx = threadIdx.x; idx < 4096; idx += 256) {
            int o = idx >> 9, k = idx & 511;
            Wt[idx] = W1[k * 8 + o];
        }
        __syncthreads();
        int warp = (blockIdx.x * 256 + threadIdx.x) >> 5;
        int lane = threadIdx.x & 31;
        int nb = warp * 4;

        float acc[4][8];
        #pragma unroll
        for (int i = 0; i < 4; i++)
            #pragma unroll
            for (int o = 0; o < 8; o++) acc[i][o] = 0.f;

        #pragma unroll
        for (int j = 0; j < 4; j++) {
            int c = 4 * lane + 128 * j;
            float4 xv[4];
            #pragma unroll
            for (int i = 0; i < 4; i++)
                xv[i] = *(const float4*)(x + (size_t)(nb + i) * 512 + c);
            #pragma unroll
            for (int o = 0; o < 8; o++) {
                float4 wv = *(const float4*)(Wt + o * 512 + c);
                #pragma unroll
                for (int i = 0; i < 4; i++)
                    acc[i][o] += xv[i].x * wv.x + xv[i].y * wv.y + xv[i].z * wv.z + xv[i].w * wv.w;
            }
        }
        float myval = 0.f;
        #pragma unroll
        for (int i = 0; i < 4; i++)
            #pragma unroll
            for (int o = 0; o < 8; o++) {
                float r = acc[i][o];
                #pragma unroll
                for (int off = 16; off; off >>= 1) r += __shfl_xor_sync(0xffffffffu, r, off);
                if (lane == i * 8 + o) myval = r;
            }
        g_t0[(size_t)nb * 8 + lane] = myval;
    } else {
        int e = (blockIdx.x - 3125) * 256 + threadIdx.x;  // exact: 12500 blocks
        int src, dst;
        if (g_flag64) { src = ei[2 * e]; dst = ei[2 * (NE + e)]; }
        else          { src = ei[e];     dst = ei[NE + e]; }
        int pos = atomicAdd(&g_cursor[dst], 1);
        g_csr[pos] = make_int2(src, __float_as_int(ew[e]));
    }
}

// ---------------- agg gather macro: fp32 8-wide table ----------------
#define GATHER_F32(TIN)                                                          \
    int s = g_rowptr[gid], e = g_rowptr[gid + 1];                                \
    float acc = 0.f;                                                             \
    int i = s;                                                                   \
    for (; i + 3 < e; i += 4) {                                                  \
        int2 a = g_csr[i], b = g_csr[i + 1], c = g_csr[i + 2], d = g_csr[i + 3]; \
        float p0 = TIN[(size_t)a.x * 8 + f] * __int_as_float(a.y);               \
        float p1 = TIN[(size_t)b.x * 8 + f] * __int_as_float(b.y);               \
        float p2 = TIN[(size_t)c.x * 8 + f] * __int_as_float(c.y);               \
        float p3 = TIN[(size_t)d.x * 8 + f] * __int_as_float(d.y);               \
        acc += (p0 + p1) + (p2 + p3);                                            \
    }                                                                            \
    for (; i < e; i++) {                                                         \
        int2 a = g_csr[i];                                                       \
        acc += TIN[(size_t)a.x * 8 + f] * __int_as_float(a.y);                   \
    }

// ---------------- agg gather macro: fp16 16-wide table (half2 per lane) ----------
#define GATHER_H16(TINH2)                                                        \
    int s = g_rowptr[gid], e = g_rowptr[gid + 1];                                \
    float acc0 = 0.f, acc1 = 0.f;                                                \
    int i = s;                                                                   \
    for (; i + 3 < e; i += 4) {                                                  \
        int2 a = g_csr[i], b = g_csr[i + 1], c = g_csr[i + 2], d = g_csr[i + 3]; \
        float2 v0 = __half22float2(TINH2[(size_t)a.x * 8 + f]);                  \
        float2 v1 = __half22float2(TINH2[(size_t)b.x * 8 + f]);                  \
        float2 v2 = __half22float2(TINH2[(size_t)c.x * 8 + f]);                  \
        float2 v3 = __half22float2(TINH2[(size_t)d.x * 8 + f]);                  \
        float wa = __int_as_float(a.y), wb = __int_as_float(b.y);                \
        float wc = __int_as_float(c.y), wd = __int_as_float(d.y);                \
        acc0 += v0.x * wa + v1.x * wb + v2.x * wc + v3.x * wd;                   \
        acc1 += v0.y * wa + v1.y * wb + v2.y * wc + v3.y * wd;                   \
    }                                                                            \
    for (; i < e; i++) {                                                         \
        int2 a = g_csr[i];                                                       \
        float2 v = __half22float2(TINH2[(size_t)a.x * 8 + f]);                   \
        float w = __int_as_float(a.y);                                           \
        acc0 += v.x * w; acc1 += v.y * w;                                        \
    }

// ---------------- layer 1: agg(t0) + b1, relu, @W2 (8->16), store half ----------
__global__ void k_agg1(const float* __restrict__ b1, const float* __restrict__ W2) {
    __shared__ float Ws[8 * 16];
    __shared__ float bs[8];
    if (threadIdx.x < 128) Ws[threadIdx.x] = W2[threadIdx.x];
    if (threadIdx.x < 8) bs[threadIdx.x] = b1[threadIdx.x];
    __syncthreads();
    int t = blockIdx.x * 256 + threadIdx.x;
    int gid = t >> 3, f = t & 7;
    GATHER_F32(g_t0)
    float h = fmaxf(acc + bs[f], 0.f);
    float o0 = 0.f, o1 = 0.f;
    #pragma unroll
    for (int k = 0; k < 8; k++) {
        float hk = __shfl_sync(0xffffffffu, h, k, 8);
        o0 += hk * Ws[k * 16 + f];
        o1 += hk * Ws[k * 16 + f + 8];
    }
    g_h1[(size_t)gid * 16 + f]     = __float2half(o0);
    g_h1[(size_t)gid * 16 + f + 8] = __float2half(o1);
}

// ---------------- layer 2: agg(h1) + b2, relu, @W3 (16->8), store fp32 ----------
__global__ void k_agg2(const float* __restrict__ b2, const float* __restrict__ W3) {
    __shared__ float Ws[16 * 8];
    __shared__ float bs[16];
    if (threadIdx.x < 128) Ws[threadIdx.x] = W3[threadIdx.x];
    if (threadIdx.x < 16) bs[threadIdx.x] = b2[threadIdx.x];
    __syncthreads();
    int t = blockIdx.x * 256 + threadIdx.x;
    int gid = t >> 3, f = t & 7;
    const __half2* tin = (const __half2*)g_h1;
    GATHER_H16(tin)
    float h0 = fmaxf(acc0 + bs[2 * f], 0.f);
    float h1 = fmaxf(acc1 + bs[2 * f + 1], 0.f);
    float out = 0.f;
    #pragma unroll
    for (int k = 0; k < 8; k++) {
        float hk0 = __shfl_sync(0xffffffffu, h0, k, 8);
        float hk1 = __shfl_sync(0xffffffffu, h1, k, 8);
        out += hk0 * Ws[(2 * k) * 8 + f] + hk1 * Ws[(2 * k + 1) * 8 + f];
    }
    g_t2[(size_t)gid * 8 + f] = out;
}

// ---------------- layer 3: agg(t2) + b3, relu, @W4 (8->10 pad16), store half -----
__global__ void k_agg3(const float* __restrict__ b3, const float* __restrict__ W4) {
    __shared__ float Ws[8 * 16];
    __shared__ float bs[8];
    if (threadIdx.x < 128) {
        int k = threadIdx.x >> 4, o = threadIdx.x & 15;
        Ws[threadIdx.x] = (o < 10) ? W4[k * 10 + o] : 0.f;
    }
    if (threadIdx.x < 8) bs[threadIdx.x] = b3[threadIdx.x];
    __syncthreads();
    int t = blockIdx.x * 256 + threadIdx.x;
    int gid = t >> 3, f = t & 7;
    GATHER_F32(g_t2)
    float h = fmaxf(acc + bs[f], 0.f);
    float o0 = 0.f, o1 = 0.f;
    #pragma unroll
    for (int k = 0; k < 8; k++) {
        float hk = __shfl_sync(0xffffffffu, h, k, 8);
        o0 += hk * Ws[k * 16 + f];
        o1 += hk * Ws[k * 16 + f + 8];
    }
    g_h3[(size_t)gid * 16 + f]     = __float2half(o0);
    g_h3[(size_t)gid * 16 + f + 8] = __float2half(o1);
}

// ---------------- layer 4: agg(h3) + b4, log_softmax over 10 classes ------------
__global__ void k_agg4(const float* __restrict__ b4, float* __restrict__ out) {
    __shared__ float bs[16];
    if (threadIdx.x < 16) bs[threadIdx.x] = (threadIdx.x < 10) ? b4[threadIdx.x] : 0.f;
    __syncthreads();
    int t = blockIdx.x * 256 + threadIdx.x;
    int gid = t >> 3, f = t & 7;
    const __half2* tin = (const __half2*)g_h3;
    GATHER_H16(tin)
    float v0 = acc0 + bs[2 * f];
    float v1 = acc1 + bs[2 * f + 1];
    bool k0 = (2 * f) < 10, k1 = (2 * f + 1) < 10;
    float m = -INFINITY;
    if (k0) m = v0;
    if (k1) m = fmaxf(m, v1);
    #pragma unroll
    for (int off = 4; off; off >>= 1) m = fmaxf(m, __shfl_xor_sync(0xffffffffu, m, off, 8));
    float e0 = k0 ? expf(v0 - m) : 0.f;
    float e1 = k1 ? expf(v1 - m) : 0.f;
    float se = e0 + e1;
    #pragma unroll
    for (int off = 4; off; off >>= 1) se += __shfl_xor_sync(0xffffffffu, se, off, 8);
    float ls = logf(se);
    if (k0) out[(size_t)gid * 10 + 2 * f]     = v0 - m - ls;
    if (k1) out[(size_t)gid * 10 + 2 * f + 1] = v1 - m - ls;
}

// ---------------- launch ----------------
extern "C" void kernel_launch(void* const* d_in, const int* in_sizes, int n_in,
                              void* d_out, int out_size) {
    const float* x  = (const float*)d_in[0];
    const int*   ei = (const int*)d_in[1];
    const float* ew = (const float*)d_in[2];
    const float* W1 = (const float*)d_in[3];
    const float* b1 = (const float*)d_in[4];
    const float* W2 = (const float*)d_in[5];
    const float* b2 = (const float*)d_in[6];
    const float* W3 = (const float*)d_in[7];
    const float* b3 = (const float*)d_in[8];
    const float* W4 = (const float*)d_in[9];
    const float* b4 = (const float*)d_in[10];
    float* out = (float*)d_out;

    void* degp;
    cudaGetSymbolAddress(&degp, g_deg);
    cudaMemsetAsync(degp, 0, NN * sizeof(int));

    k_detect<<<1, 32>>>(ei);
    k_count<<<NE / 256, 256>>>(ei);
    k_scanA<<<98, 1024>>>();
    k_scanCB<<<(NN + 255) / 256, 256>>>();
    k_fused<<<3125 + NE / 256, 256>>>(x, W1, ei, ew);   // gemm1 || scatter

    k_agg1<<<NN * 8 / 256, 256>>>(b1, W2);
    k_agg2<<<NN * 8 / 256, 256>>>(b2, W3);
    k_agg3<<<NN * 8 / 256, 256>>>(b3, W4);
    k_agg4<<<NN * 8 / 256, 256>>>(b4, out);
}

// round 7
// speedup vs baseline: 1.0772x; 1.0204x over previous
#include <cuda_runtime.h>
#include <cuda_fp16.h>
#include <math.h>

#define NN 100000
#define NE 3200000

// ---------------- device scratch ----------------
__device__ int    g_flag64;
__device__ int    g_deg[NN];
__device__ int    g_rowptr[NN + 1];
__device__ int    g_cursor[NN];
__device__ int    g_bsum[128];
__device__ int2   g_csr[NE];           // {src, weight-bits}, bucketed by dst
__device__ float  g_t0[NN * 8];        // x@W1                     (fp32, 8-wide)
__device__ __half g_h1[NN * 16];       // relu(agg1+b1)@W2         (fp16, 16-wide)
__device__ float  g_t2[NN * 8];        // relu(agg2+b2)@W3         (fp32, 8-wide)
__device__ __half g_h3[NN * 16];       // relu(agg3+b3)@W4 pad16   (fp16, 16-wide)

// ---------------- dtype detection: int64 vs int32 edge_index ----------------
__global__ void k_detect(const int* __restrict__ ei) {
    int v = 0;
    for (int i = threadIdx.x; i < 512; i += 32) v |= ei[2 * i + 1];
    for (int o = 16; o; o >>= 1) v |= __shfl_xor_sync(0xffffffffu, v, o);
    if (threadIdx.x == 0) g_flag64 = (v == 0) ? 1 : 0;
}

// ---------------- degree count (reads only dst half of edge_index) ----------------
__global__ void k_count(const int* __restrict__ ei) {
    int e = blockIdx.x * blockDim.x + threadIdx.x;  // NE divisible by 256
    int dst = g_flag64 ? ei[2 * (NE + e)] : ei[NE + e];
    atomicAdd(&g_deg[dst], 1);
}

// ---------------- scan A: block-local exclusive scan + block sums ----------------
__global__ void k_scanA() {
    __shared__ int wsum[32];
    int i = blockIdx.x * 1024 + threadIdx.x;
    int lane = threadIdx.x & 31, wid = threadIdx.x >> 5;
    int val = (i < NN) ? g_deg[i] : 0;
    int v = val;
    #pragma unroll
    for (int o = 1; o < 32; o <<= 1) {
        int u = __shfl_up_sync(0xffffffffu, v, o);
        if (lane >= o) v += u;
    }
    if (lane == 31) wsum[wid] = v;
    __syncthreads();
    if (wid == 0) {
        int w = wsum[lane];
        #pragma unroll
        for (int o = 1; o < 32; o <<= 1) {
            int u = __shfl_up_sync(0xffffffffu, w, o);
            if (lane >= o) w += u;
        }
        wsum[lane] = w;
    }
    __syncthreads();
    int incl = v + (wid ? wsum[wid - 1] : 0);
    if (i < NN) g_rowptr[i] = incl - val;
    if (threadIdx.x == 1023) g_bsum[blockIdx.x] = incl;
}

// ---------------- scan C (scanB folded in) ----------------
__global__ void k_scanCB() {
    __shared__ int s[128];
    int t = threadIdx.x;
    if (t < 128) s[t] = (t < 98) ? g_bsum[t] : 0;
    __syncthreads();
    if (t == 0) {
        int r = 0;
        for (int i = 0; i < 98; i++) { int x = s[i]; s[i] = r; r += x; }
    }
    __syncthreads();
    int i = blockIdx.x * 256 + t;
    if (i < NN) {
        int rp = g_rowptr[i] + s[i >> 10];
        g_rowptr[i] = rp;
        g_cursor[i] = rp;
    }
    if (i == 0) g_rowptr[NN] = NE;
}

// ---------------- fused: gemm1 (blocks 0..3124) || scatter (rest) ----------------
__global__ void k_fused(const float* __restrict__ x, const float* __restrict__ W1,
                        const int* __restrict__ ei, const float* __restrict__ ew) {
    __shared__ float Wt[8 * 512];
    if (blockIdx.x < 3125) {
        for (int idx = threadIdx.x; idx < 4096; idx += 256) {
            int o = idx >> 9, k = idx & 511;
            Wt[idx] = W1[k * 8 + o];
        }
        __syncthreads();
        int warp = (blockIdx.x * 256 + threadIdx.x) >> 5;
        int lane = threadIdx.x & 31;
        int nb = warp * 4;

        float acc[4][8];
        #pragma unroll
        for (int i = 0; i < 4; i++)
            #pragma unroll
            for (int o = 0; o < 8; o++) acc[i][o] = 0.f;

        #pragma unroll
        for (int j = 0; j < 4; j++) {
            int c = 4 * lane + 128 * j;
            float4 xv[4];
            #pragma unroll
            for (int i = 0; i < 4; i++)
                xv[i] = *(const float4*)(x + (size_t)(nb + i) * 512 + c);
            #pragma unroll
            for (int o = 0; o < 8; o++) {
                float4 wv = *(const float4*)(Wt + o * 512 + c);
                #pragma unroll
                for (int i = 0; i < 4; i++)
                    acc[i][o] += xv[i].x * wv.x + xv[i].y * wv.y + xv[i].z * wv.z + xv[i].w * wv.w;
            }
        }
        float myval = 0.f;
        #pragma unroll
        for (int i = 0; i < 4; i++)
            #pragma unroll
            for (int o = 0; o < 8; o++) {
                float r = acc[i][o];
                #pragma unroll
                for (int off = 16; off; off >>= 1) r += __shfl_xor_sync(0xffffffffu, r, off);
                if (lane == i * 8 + o) myval = r;
            }
        g_t0[(size_t)nb * 8 + lane] = myval;
    } else {
        int e = (blockIdx.x - 3125) * 256 + threadIdx.x;
        int src, dst;
        if (g_flag64) { src = ei[2 * e]; dst = ei[2 * (NE + e)]; }
        else          { src = ei[e];     dst = ei[NE + e]; }
        int pos = atomicAdd(&g_cursor[dst], 1);
        g_csr[pos] = make_int2(src, __float_as_int(ew[e]));
    }
}

// ================= agg gathers: coalesced CSR + width-8 shfl broadcast ===========
// Group of 8 lanes shares one node (gid); lane f owns feature(s) f.
// CSR loads: 8 consecutive int2 per group (coalesced 64B), then shfl-broadcast.
// gmask = the 8-lane mask of this group (needed: groups diverge in loop counts).

// fp32 8-wide table: acc (1 float)
#define GATHER_F32(TIN)                                                          \
    int s = g_rowptr[gid], e = g_rowptr[gid + 1];                                \
    unsigned gmask = 0xFFu << (threadIdx.x & 24);                                \
    float acc = 0.f;                                                             \
    int i = s;                                                                   \
    for (; i + 8 <= e; i += 8) {                                                 \
        int2 my = g_csr[i + f];                                                  \
        _Pragma("unroll")                                                        \
        for (int k = 0; k < 8; k++) {                                            \
            int   sk = __shfl_sync(gmask, my.x, k, 8);                           \
            float wk = __int_as_float(__shfl_sync(gmask, my.y, k, 8));           \
            acc += TIN[(size_t)sk * 8 + f] * wk;                                 \
        }                                                                        \
    }                                                                            \
    int rem = e - i;                                                             \
    if (rem) {                                                                   \
        int2 my = make_int2(0, 0);                                               \
        if (f < rem) my = g_csr[i + f];                                          \
        _Pragma("unroll")                                                        \
        for (int k = 0; k < 7; k++) {                                            \
            int   sk = __shfl_sync(gmask, my.x, k, 8);                           \
            float wk = __int_as_float(__shfl_sync(gmask, my.y, k, 8));           \
            if (k < rem) acc += TIN[(size_t)sk * 8 + f] * wk;                    \
        }                                                                        \
    }

// fp16 16-wide table (half2 per lane): acc0/acc1
#define GATHER_H16(TINH2)                                                        \
    int s = g_rowptr[gid], e = g_rowptr[gid + 1];                                \
    unsigned gmask = 0xFFu << (threadIdx.x & 24);                                \
    float acc0 = 0.f, acc1 = 0.f;                                                \
    int i = s;                                                                   \
    for (; i + 8 <= e; i += 8) {                                                 \
        int2 my = g_csr[i + f];                                                  \
        _Pragma("unroll")                                                        \
        for (int k = 0; k < 8; k++) {                                            \
            int   sk = __shfl_sync(gmask, my.x, k, 8);                           \
            float wk = __int_as_float(__shfl_sync(gmask, my.y, k, 8));           \
            float2 v = __half22float2(TINH2[(size_t)sk * 8 + f]);                \
            acc0 += v.x * wk;  acc1 += v.y * wk;                                 \
        }                                                                        \
    }                                                                            \
    int rem = e - i;                                                             \
    if (rem) {                                                                   \
        int2 my = make_int2(0, 0);                                               \
        if (f < rem) my = g_csr[i + f];                                          \
        _Pragma("unroll")                                                        \
        for (int k = 0; k < 7; k++) {                                            \
            int   sk = __shfl_sync(gmask, my.x, k, 8);                           \
            float wk = __int_as_float(__shfl_sync(gmask, my.y, k, 8));           \
            if (k < rem) {                                                       \
                float2 v = __half22float2(TINH2[(size_t)sk * 8 + f]);            \
                acc0 += v.x * wk;  acc1 += v.y * wk;                             \
            }                                                                    \
        }                                                                        \
    }

// ---------------- layer 1: agg(t0) + b1, relu, @W2 (8->16), store half ----------
__global__ void k_agg1(const float* __restrict__ b1, const float* __restrict__ W2) {
    __shared__ float Ws[8 * 16];
    __shared__ float bs[8];
    if (threadIdx.x < 128) Ws[threadIdx.x] = W2[threadIdx.x];
    if (threadIdx.x < 8) bs[threadIdx.x] = b1[threadIdx.x];
    __syncthreads();
    int t = blockIdx.x * 256 + threadIdx.x;
    int gid = t >> 3, f = t & 7;
    GATHER_F32(g_t0)
    float h = fmaxf(acc + bs[f], 0.f);
    float o0 = 0.f, o1 = 0.f;
    #pragma unroll
    for (int k = 0; k < 8; k++) {
        float hk = __shfl_sync(0xffffffffu, h, k, 8);
        o0 += hk * Ws[k * 16 + f];
        o1 += hk * Ws[k * 16 + f + 8];
    }
    g_h1[(size_t)gid * 16 + f]     = __float2half(o0);
    g_h1[(size_t)gid * 16 + f + 8] = __float2half(o1);
}

// ---------------- layer 2: agg(h1) + b2, relu, @W3 (16->8), store fp32 ----------
__global__ void k_agg2(const float* __restrict__ b2, const float* __restrict__ W3) {
    __shared__ float Ws[16 * 8];
    __shared__ float bs[16];
    if (threadIdx.x < 128) Ws[threadIdx.x] = W3[threadIdx.x];
    if (threadIdx.x < 16) bs[threadIdx.x] = b2[threadIdx.x];
    __syncthreads();
    int t = blockIdx.x * 256 + threadIdx.x;
    int gid = t >> 3, f = t & 7;
    const __half2* tin = (const __half2*)g_h1;
    GATHER_H16(tin)
    float h0 = fmaxf(acc0 + bs[2 * f], 0.f);
    float h1 = fmaxf(acc1 + bs[2 * f + 1], 0.f);
    float out = 0.f;
    #pragma unroll
    for (int k = 0; k < 8; k++) {
        float hk0 = __shfl_sync(0xffffffffu, h0, k, 8);
        float hk1 = __shfl_sync(0xffffffffu, h1, k, 8);
        out += hk0 * Ws[(2 * k) * 8 + f] + hk1 * Ws[(2 * k + 1) * 8 + f];
    }
    g_t2[(size_t)gid * 8 + f] = out;
}

// ---------------- layer 3: agg(t2) + b3, relu, @W4 (8->10 pad16), store half -----
__global__ void k_agg3(const float* __restrict__ b3, const float* __restrict__ W4) {
    __shared__ float Ws[8 * 16];
    __shared__ float bs[8];
    if (threadIdx.x < 128) {
        int k = threadIdx.x >> 4, o = threadIdx.x & 15;
        Ws[threadIdx.x] = (o < 10) ? W4[k * 10 + o] : 0.f;
    }
    if (threadIdx.x < 8) bs[threadIdx.x] = b3[threadIdx.x];
    __syncthreads();
    int t = blockIdx.x * 256 + threadIdx.x;
    int gid = t >> 3, f = t & 7;
    GATHER_F32(g_t2)
    float h = fmaxf(acc + bs[f], 0.f);
    float o0 = 0.f, o1 = 0.f;
    #pragma unroll
    for (int k = 0; k < 8; k++) {
        float hk = __shfl_sync(0xffffffffu, h, k, 8);
        o0 += hk * Ws[k * 16 + f];
        o1 += hk * Ws[k * 16 + f + 8];
    }
    g_h3[(size_t)gid * 16 + f]     = __float2half(o0);
    g_h3[(size_t)gid * 16 + f + 8] = __float2half(o1);
}

// ---------------- layer 4: agg(h3) + b4, log_softmax over 10 classes ------------
__global__ void k_agg4(const float* __restrict__ b4, float* __restrict__ out) {
    __shared__ float bs[16];
    if (threadIdx.x < 16) bs[threadIdx.x] = (threadIdx.x < 10) ? b4[threadIdx.x] : 0.f;
    __syncthreads();
    int t = blockIdx.x * 256 + threadIdx.x;
    int gid = t >> 3, f = t & 7;
    const __half2* tin = (const __half2*)g_h3;
    GATHER_H16(tin)
    float v0 = acc0 + bs[2 * f];
    float v1 = acc1 + bs[2 * f + 1];
    bool k0 = (2 * f) < 10, k1 = (2 * f + 1) < 10;
    float m = -INFINITY;
    if (k0) m = v0;
    if (k1) m = fmaxf(m, v1);
    #pragma unroll
    for (int off = 4; off; off >>= 1) m = fmaxf(m, __shfl_xor_sync(0xffffffffu, m, off, 8));
    float e0 = k0 ? expf(v0 - m) : 0.f;
    float e1 = k1 ? expf(v1 - m) : 0.f;
    float se = e0 + e1;
    #pragma unroll
    for (int off = 4; off; off >>= 1) se += __shfl_xor_sync(0xffffffffu, se, off, 8);
    float ls = logf(se);
    if (k0) out[(size_t)gid * 10 + 2 * f]     = v0 - m - ls;
    if (k1) out[(size_t)gid * 10 + 2 * f + 1] = v1 - m - ls;
}

// ---------------- launch ----------------
extern "C" void kernel_launch(void* const* d_in, const int* in_sizes, int n_in,
                              void* d_out, int out_size) {
    const float* x  = (const float*)d_in[0];
    const int*   ei = (const int*)d_in[1];
    const float* ew = (const float*)d_in[2];
    const float* W1 = (const float*)d_in[3];
    const float* b1 = (const float*)d_in[4];
    const float* W2 = (const float*)d_in[5];
    const float* b2 = (const float*)d_in[6];
    const float* W3 = (const float*)d_in[7];
    const float* b3 = (const float*)d_in[8];
    const float* W4 = (const float*)d_in[9];
    const float* b4 = (const float*)d_in[10];
    float* out = (float*)d_out;

    void* degp;
    cudaGetSymbolAddress(&degp, g_deg);
    cudaMemsetAsync(degp, 0, NN * sizeof(int));

    k_detect<<<1, 32>>>(ei);
    k_count<<<NE / 256, 256>>>(ei);
    k_scanA<<<98, 1024>>>();
    k_scanCB<<<(NN + 255) / 256, 256>>>();
    k_fused<<<3125 + NE / 256, 256>>>(x, W1, ei, ew);   // gemm1 || scatter

    k_agg1<<<NN * 8 / 256, 256>>>(b1, W2);
    k_agg2<<<NN * 8 / 256, 256>>>(b2, W3);
    k_agg3<<<NN * 8 / 256, 256>>>(b3, W4);
    k_agg4<<<NN * 8 / 256, 256>>>(b4, out);
}